// round 7
// baseline (speedup 1.0000x reference)
#include <cuda_runtime.h>

// SCVC: out[n, g*OG+o, p, q] = C[g,o]*x[n,g,p]*y[n,g,q] + a[n,g,o,p] + b[n,g,o,q]
//   a[p] = wA0*x[p-1] + wA1*x[p+1]  (zero boundary)
//   b[q] = wB0*y[q-1] + wB1*y[q+1]  (zero boundary)
// Shapes: N=8, G=8, OG=16, DX=DY=256. Output = 256 MiB fp32 -> store-bound.
// R7: R5 grid (16384 blocks, max occupancy) + single barrier. ssap precomputed
// pre-barrier (independent of sy), b[q] in registers from y halo. Plain
// write-back stores (let L2 aggregate evictions).

#define N_  8
#define G_  8
#define OG_ 16
#define DX_ 256
#define DY_ 256
#define PT  16   // p-rows per block

__global__ __launch_bounds__(256) void scvc_kernel(
    const float* __restrict__ x,   // (N, G, DX)
    const float* __restrict__ y,   // (N, G, DY)
    const float* __restrict__ C,   // (G, OG)
    const float* __restrict__ wA,  // (G, OG, 2)
    const float* __restrict__ wB,  // (G, OG, 2)
    float* __restrict__ out)       // (N, G*OG, DX, DY)
{
    __shared__ float  sy[DY_];
    __shared__ float2 ssap[PT];   // (s = C*x[p], ap = wA0*x[p-1] + wA1*x[p+1])

    const int b  = blockIdx.x;
    const int pt = b & 15;            // DX_/PT = 16 tiles
    const int o  = (b >> 4) & 15;     // OG_ = 16
    const int g  = (b >> 8) & 7;      // G_  = 8
    const int n  = b >> 11;           // N_  = 8

    const int tid = threadIdx.x;
    const int ng = n * G_ + g;
    const int go = g * OG_ + o;

    // Stage y row.
    sy[tid] = y[ng * DY_ + tid];

    // Per-row scalars (independent of sy) — before the single barrier.
    if (tid < PT) {
        const float* __restrict__ xrow = x + ng * DX_;
        const float Cgo = C[go];
        const float wA0 = wA[go * 2 + 0];
        const float wA1 = wA[go * 2 + 1];
        const int p = pt * PT + tid;
        const float xp = xrow[p];
        const float xl = (p > 0)       ? xrow[p - 1] : 0.0f;
        const float xr = (p < DX_ - 1) ? xrow[p + 1] : 0.0f;
        ssap[tid] = make_float2(Cgo * xp, wA0 * xl + wA1 * xr);
    }
    const float wB0 = wB[go * 2 + 0];
    const float wB1 = wB[go * 2 + 1];
    __syncthreads();

    // Thread layout: r = row-within-4, c = float4 column (64 per row).
    const int r = tid >> 6;
    const int c = tid & 63;

    // y fragment + halo; b[q] computed in registers (no second barrier).
    const float4 yv  = reinterpret_cast<const float4*>(sy)[c];
    const float  yl0 = (c > 0)  ? sy[4 * c - 1] : 0.0f;
    const float  yr3 = (c < 63) ? sy[4 * c + 4] : 0.0f;

    float4 bv;
    bv.x = wB0 * yl0  + wB1 * yv.y;
    bv.y = wB0 * yv.x + wB1 * yv.z;
    bv.z = wB0 * yv.y + wB1 * yv.w;
    bv.w = wB0 * yv.z + wB1 * yr3;

    float* __restrict__ obase =
        out + ((size_t)ng * OG_ + o) * (size_t)(DX_ * DY_);

    #pragma unroll
    for (int it = 0; it < PT / 4; ++it) {
        const int p = pt * PT + it * 4 + r;
        const float2 sa = ssap[it * 4 + r];  // broadcast LDS.64
        const float s  = sa.x;
        const float ap = sa.y;

        float4 v;
        v.x = fmaf(s, yv.x, ap + bv.x);
        v.y = fmaf(s, yv.y, ap + bv.y);
        v.z = fmaf(s, yv.z, ap + bv.z);
        v.w = fmaf(s, yv.w, ap + bv.w);

        // Plain write-back store: let L2 aggregate evictions.
        reinterpret_cast<float4*>(obase + (size_t)p * DY_)[c] = v;
    }
}

extern "C" void kernel_launch(void* const* d_in, const int* in_sizes, int n_in,
                              void* d_out, int out_size)
{
    const float* x  = (const float*)d_in[0];
    const float* y  = (const float*)d_in[1];
    const float* C  = (const float*)d_in[2];
    const float* wA = (const float*)d_in[3];
    const float* wB = (const float*)d_in[4];
    float* out = (float*)d_out;

    const int nblocks = N_ * G_ * OG_ * (DX_ / PT);  // 16384
    scvc_kernel<<<nblocks, 256>>>(x, y, C, wA, wB, out);
}

// round 9
// speedup vs baseline: 1.0827x; 1.0827x over previous
#include <cuda_runtime.h>

// SCVC: out[n, g*OG+o, p, q] = C[g,o]*x[n,g,p]*y[n,g,q] + a[n,g,o,p] + b[n,g,o,q]
//   a[p] = wA0*x[p-1] + wA1*x[p+1]  (zero boundary)
//   b[q] = wB0*y[q-1] + wB1*y[q+1]  (zero boundary)
// Shapes: N=8, G=8, OG=16, DX=DY=256. Output = 256 MiB fp32 -> HBM-store floor.
// R8: best-of-all-rounds: 16384-block grid (max occupancy), single barrier,
// b[q] in registers, per-row scalars hoisted to registers pre-loop so the
// 4 STG.128 issue back-to-back (max store MLP), __stcs streaming stores.

#define N_  8
#define G_  8
#define OG_ 16
#define DX_ 256
#define DY_ 256
#define PT  16   // p-rows per block

__global__ __launch_bounds__(256) void scvc_kernel(
    const float* __restrict__ x,   // (N, G, DX)
    const float* __restrict__ y,   // (N, G, DY)
    const float* __restrict__ C,   // (G, OG)
    const float* __restrict__ wA,  // (G, OG, 2)
    const float* __restrict__ wB,  // (G, OG, 2)
    float* __restrict__ out)       // (N, G*OG, DX, DY)
{
    __shared__ float  sy[DY_];
    __shared__ float2 ssap[PT];   // (s = C*x[p], ap = wA0*x[p-1] + wA1*x[p+1])

    const int b  = blockIdx.x;
    const int pt = b & 15;            // DX_/PT = 16 tiles
    const int o  = (b >> 4) & 15;     // OG_ = 16
    const int g  = (b >> 8) & 7;      // G_  = 8
    const int n  = b >> 11;           // N_  = 8

    const int tid = threadIdx.x;
    const int ng = n * G_ + g;
    const int go = g * OG_ + o;

    // Stage y row.
    sy[tid] = y[ng * DY_ + tid];

    // Per-row scalars (independent of sy) — before the single barrier.
    if (tid < PT) {
        const float* __restrict__ xrow = x + ng * DX_;
        const float Cgo = C[go];
        const float wA0 = wA[go * 2 + 0];
        const float wA1 = wA[go * 2 + 1];
        const int p = pt * PT + tid;
        const float xp = xrow[p];
        const float xl = (p > 0)       ? xrow[p - 1] : 0.0f;
        const float xr = (p < DX_ - 1) ? xrow[p + 1] : 0.0f;
        ssap[tid] = make_float2(Cgo * xp, wA0 * xl + wA1 * xr);
    }
    const float wB0 = wB[go * 2 + 0];
    const float wB1 = wB[go * 2 + 1];
    __syncthreads();

    // Thread layout: r = row-within-4, c = float4 column (64 per row).
    const int r = tid >> 6;
    const int c = tid & 63;

    // y fragment + halo; b[q] computed in registers (no second barrier).
    const float4 yv  = reinterpret_cast<const float4*>(sy)[c];
    const float  yl0 = (c > 0)  ? sy[4 * c - 1] : 0.0f;
    const float  yr3 = (c < 63) ? sy[4 * c + 4] : 0.0f;

    float4 bv;
    bv.x = wB0 * yl0  + wB1 * yv.y;
    bv.y = wB0 * yv.x + wB1 * yv.z;
    bv.z = wB0 * yv.y + wB1 * yv.w;
    bv.w = wB0 * yv.z + wB1 * yr3;

    // Hoist all 4 per-row scalar pairs into registers (broadcast LDS.64 x4),
    // then compute all 4 output vectors, then issue 4 back-to-back stores.
    float2 sa[4];
    #pragma unroll
    for (int it = 0; it < 4; ++it)
        sa[it] = ssap[it * 4 + r];

    float4 v[4];
    #pragma unroll
    for (int it = 0; it < 4; ++it) {
        const float s  = sa[it].x;
        const float ap = sa[it].y;
        v[it].x = fmaf(s, yv.x, ap + bv.x);
        v[it].y = fmaf(s, yv.y, ap + bv.y);
        v[it].z = fmaf(s, yv.z, ap + bv.z);
        v[it].w = fmaf(s, yv.w, ap + bv.w);
    }

    float* __restrict__ obase =
        out + ((size_t)ng * OG_ + o) * (size_t)(DX_ * DY_);

    #pragma unroll
    for (int it = 0; it < 4; ++it) {
        const int p = pt * PT + it * 4 + r;
        // Streaming store: write-once output, evict-first policy.
        __stcs(reinterpret_cast<float4*>(obase + (size_t)p * DY_) + c, v[it]);
    }
}

extern "C" void kernel_launch(void* const* d_in, const int* in_sizes, int n_in,
                              void* d_out, int out_size)
{
    const float* x  = (const float*)d_in[0];
    const float* y  = (const float*)d_in[1];
    const float* C  = (const float*)d_in[2];
    const float* wA = (const float*)d_in[3];
    const float* wB = (const float*)d_in[4];
    float* out = (float*)d_out;

    const int nblocks = N_ * G_ * OG_ * (DX_ / PT);  // 16384
    scvc_kernel<<<nblocks, 256>>>(x, y, C, wA, wB, out);
}